// round 6
// baseline (speedup 1.0000x reference)
#include <cuda_runtime.h>

// ---------------- static scratch (no allocation allowed) ----------------
#define NMAX 200000
#define EMAX 400000
#define FMAX 256
#define GMAX 8192
#define EPS_BN 1e-5f

__device__ float d_hA[(size_t)NMAX * FMAX];   // aggregation output / GEMM A (tf32-rounded)
__device__ float d_hB[(size_t)NMAX * FMAX];   // GEMM output (raw, pre-BN)
__device__ float d_dis[NMAX];
__device__ unsigned int d_deg[NMAX];          // 1 + in-degree
__device__ float d_stat[4 * FMAX];            // sum | sumsq | scale | shift
__device__ float d_pool[(size_t)GMAX * FMAX];
__device__ float d_Wt[FMAX * FMAX];           // tf32-rounded weight staging
__device__ unsigned int d_cnt[GMAX];
__device__ int d_goff[GMAX];
__device__ int d_ei32[2 * EMAX];
__device__ int d_batch32[NMAX];
__device__ int d_is64;
__device__ int d_off[NMAX];
__device__ unsigned int d_cur[NMAX];
__device__ int d_srcs[EMAX];
__device__ int d_bsum[1024];
__device__ int d_bsum2[64];

// ---------------- small helpers ----------------
__device__ __forceinline__ float f2tf_f(float f) {
    unsigned r;
    asm("cvt.rna.tf32.f32 %0, %1;" : "=r"(r) : "f"(f));
    return __uint_as_float(r);
}
__device__ __forceinline__ unsigned smem_u32(const void* p) {
    return (unsigned)__cvta_generic_to_shared(p);
}
__device__ __forceinline__ void cpa16(unsigned dst, const void* src, bool pred) {
    int sz = pred ? 16 : 0;
    asm volatile("cp.async.ca.shared.global [%0], [%1], 16, %2;\n"
                 :: "r"(dst), "l"(src), "r"(sz));
}
__device__ __forceinline__ void cpa_commit() { asm volatile("cp.async.commit_group;\n"); }
template <int NWait>
__device__ __forceinline__ void cpa_wait() { asm volatile("cp.async.wait_group %0;\n" :: "n"(NWait)); }

__device__ __forceinline__ void mma_tf32(float* c, const unsigned* a, const unsigned* b) {
    asm volatile(
        "mma.sync.aligned.m16n8k8.row.col.f32.tf32.tf32.f32 "
        "{%0,%1,%2,%3}, {%4,%5,%6,%7}, {%8,%9}, {%0,%1,%2,%3};"
        : "+f"(c[0]), "+f"(c[1]), "+f"(c[2]), "+f"(c[3])
        : "r"(a[0]), "r"(a[1]), "r"(a[2]), "r"(a[3]), "r"(b[0]), "r"(b[1]));
}

// ---------------- index dtype sniffing + conversion ----------------
__global__ void k_sniff(const void* ei) {
    const int* p = (const int*)ei;
    int ok64 = 1;
    for (int j = 0; j < 64; j++)
        if (p[2 * j + 1] != 0) ok64 = 0;
    d_is64 = ok64;
}
__global__ void k_conv_ei(const void* ei, int E2) {
    int i = blockIdx.x * blockDim.x + threadIdx.x;
    if (i < E2)
        d_ei32[i] = d_is64 ? (int)((const long long*)ei)[i] : ((const int*)ei)[i];
}
__global__ void k_conv_batch(const void* b, int N) {
    int i = blockIdx.x * blockDim.x + threadIdx.x;
    if (i < N) {
        d_batch32[i] = d_is64 ? (int)((const long long*)b)[i] : ((const int*)b)[i];
        d_deg[i] = 1u;   // self loop
        d_cur[i] = 0u;
    }
    if (i < 512) d_stat[i] = 0.f;   // initial stats zero (layer 1)
}

// ---------------- degree / norm ----------------
__global__ void k_count_deg(int E) {
    int e = blockIdx.x * blockDim.x + threadIdx.x;
    if (e < E) atomicAdd(&d_deg[d_ei32[E + e]], 1u);
}
__global__ void k_dis(int N) {
    int i = blockIdx.x * blockDim.x + threadIdx.x;
    if (i < N) d_dis[i] = rsqrtf((float)d_deg[i]);
}

// ---------------- CSR build (exclusive scan of in-degree) ----------
__global__ void k_scan1(int N) {
    __shared__ int sh[256];
    int i = blockIdx.x * 256 + threadIdx.x;
    int v = (i < N) ? (int)d_deg[i] - 1 : 0;
    sh[threadIdx.x] = v;
    __syncthreads();
    for (int o = 128; o > 0; o >>= 1) {
        if (threadIdx.x < o) sh[threadIdx.x] += sh[threadIdx.x + o];
        __syncthreads();
    }
    if (threadIdx.x == 0) d_bsum[blockIdx.x] = sh[0];
}
__global__ void k_scan2(int nb) {
    if (threadIdx.x == 0 && blockIdx.x == 0) {
        int run = 0;
        for (int b = 0; b < nb; b++) { int t = d_bsum[b]; d_bsum[b] = run; run += t; }
    }
}
__global__ void k_scan3(int N) {
    __shared__ int sh[256];
    int i = blockIdx.x * 256 + threadIdx.x;
    int v = (i < N) ? (int)d_deg[i] - 1 : 0;
    sh[threadIdx.x] = v;
    __syncthreads();
    for (int o = 1; o < 256; o <<= 1) {
        int t = (threadIdx.x >= o) ? sh[threadIdx.x - o] : 0;
        __syncthreads();
        sh[threadIdx.x] += t;
        __syncthreads();
    }
    if (i < N) d_off[i] = d_bsum[blockIdx.x] + sh[threadIdx.x] - v;
}
__global__ void k_fill(int E) {
    int e = blockIdx.x * blockDim.x + threadIdx.x;
    if (e < E) {
        int s = d_ei32[e], d = d_ei32[E + e];
        int pos = d_off[d] + (int)atomicAdd(&d_cur[d], 1u);
        d_srcs[pos] = s;
    }
}

// ---------------- graph-offset scan over d_cnt ----------
__global__ void k_gscan1(int G) {
    __shared__ int sh[256];
    int i = blockIdx.x * 256 + threadIdx.x;
    int v = (i < G) ? (int)d_cnt[i] : 0;
    sh[threadIdx.x] = v;
    __syncthreads();
    for (int o = 128; o > 0; o >>= 1) {
        if (threadIdx.x < o) sh[threadIdx.x] += sh[threadIdx.x + o];
        __syncthreads();
    }
    if (threadIdx.x == 0) d_bsum2[blockIdx.x] = sh[0];
}
__global__ void k_gscan2(int nb) {
    if (threadIdx.x == 0 && blockIdx.x == 0) {
        int run = 0;
        for (int b = 0; b < nb; b++) { int t = d_bsum2[b]; d_bsum2[b] = run; run += t; }
    }
}
__global__ void k_gscan3(int G) {
    __shared__ int sh[256];
    int i = blockIdx.x * 256 + threadIdx.x;
    int v = (i < G) ? (int)d_cnt[i] : 0;
    sh[threadIdx.x] = v;
    __syncthreads();
    for (int o = 1; o < 256; o <<= 1) {
        int t = (threadIdx.x >= o) ? sh[threadIdx.x - o] : 0;
        __syncthreads();
        sh[threadIdx.x] += t;
        __syncthreads();
    }
    if (i < G) d_goff[i] = d_bsum2[blockIdx.x] + sh[threadIdx.x] - v;
}

// ---------------- aggregation (gather form) ----------------
__global__ void k_gather9(const float* __restrict__ x, int N) {
    int i = blockIdx.x * blockDim.x + threadIdx.x;
    if (i >= N) return;
    float di = d_dis[i];
    float acc[9];
    const float* xi = x + (size_t)i * 9;
#pragma unroll
    for (int f = 0; f < 9; f++) acc[f] = di * di * xi[f];
    int beg = d_off[i], cnt = (int)d_deg[i] - 1;
    for (int j = 0; j < cnt; j++) {
        int s = d_srcs[beg + j];
        float w = d_dis[s] * di;
        const float* xs = x + (size_t)s * 9;
#pragma unroll
        for (int f = 0; f < 9; f++) acc[f] += w * xs[f];
    }
    float* o = d_hA + (size_t)i * 9;
#pragma unroll
    for (int f = 0; f < 9; f++) o[f] = acc[f];
}
// layers 2/3: warp per node, BN scale/shift + ReLU fused; output tf32-rounded.
__global__ void k_gather(int N, int F) {
    int w = (blockIdx.x * blockDim.x + threadIdx.x) >> 5;
    int lane = threadIdx.x & 31;
    if (w >= N) return;
    int C4 = F >> 7;
    float di = d_dis[w];
    float4 sc[2], sh[2], acc[2];
#pragma unroll
    for (int c = 0; c < 2; c++) {
        if (c < C4) {
            int col = c * 128 + lane * 4;
            sc[c] = *(const float4*)&d_stat[512 + col];
            sh[c] = *(const float4*)&d_stat[768 + col];
        }
    }
    {
        float ww = di * di;
        const float4* row = (const float4*)(d_hB + (size_t)w * F);
#pragma unroll
        for (int c = 0; c < 2; c++) {
            if (c < C4) {
                float4 v = row[c * 32 + lane];
                acc[c].x = ww * fmaxf(fmaf(v.x, sc[c].x, sh[c].x), 0.f);
                acc[c].y = ww * fmaxf(fmaf(v.y, sc[c].y, sh[c].y), 0.f);
                acc[c].z = ww * fmaxf(fmaf(v.z, sc[c].z, sh[c].z), 0.f);
                acc[c].w = ww * fmaxf(fmaf(v.w, sc[c].w, sh[c].w), 0.f);
            }
        }
    }
    int beg = d_off[w], cnt = (int)d_deg[w] - 1;
    for (int j = 0; j < cnt; j++) {
        int s = d_srcs[beg + j];
        float we = d_dis[s] * di;
        const float4* row = (const float4*)(d_hB + (size_t)s * F);
#pragma unroll
        for (int c = 0; c < 2; c++) {
            if (c < C4) {
                float4 v = row[c * 32 + lane];
                acc[c].x = fmaf(we, fmaxf(fmaf(v.x, sc[c].x, sh[c].x), 0.f), acc[c].x);
                acc[c].y = fmaf(we, fmaxf(fmaf(v.y, sc[c].y, sh[c].y), 0.f), acc[c].y);
                acc[c].z = fmaf(we, fmaxf(fmaf(v.z, sc[c].z, sh[c].z), 0.f), acc[c].z);
                acc[c].w = fmaf(we, fmaxf(fmaf(v.w, sc[c].w, sh[c].w), 0.f), acc[c].w);
            }
        }
    }
    float4* o = (float4*)(d_hA + (size_t)w * F);
#pragma unroll
    for (int c = 0; c < 2; c++) {
        if (c < C4) {
            float4 r;
            r.x = f2tf_f(acc[c].x); r.y = f2tf_f(acc[c].y);
            r.z = f2tf_f(acc[c].z); r.w = f2tf_f(acc[c].w);
            o[c * 32 + lane] = r;
        }
    }
}

// ---------------- layer-1 GEMM (fp32 FMA) with fused stats ----------------
__global__ void __launch_bounds__(256) k_gemm1(const float* __restrict__ W,
                                               const float* __restrict__ b, int N) {
    __shared__ float sW[9 * 128];
    __shared__ float sb[128];
    __shared__ float sA[64 * 9];
    __shared__ float sstat[256];
    int tid = threadIdx.x;
    for (int i = tid; i < 9 * 128; i += 256) sW[i] = W[i];
    if (tid < 128) sb[tid] = b[tid];
    sstat[tid] = 0.f;
    int row0 = blockIdx.x * 64;
    for (int i = tid; i < 576; i += 256) {
        int r = i / 9, c = i - r * 9;
        int row = row0 + r;
        sA[i] = (row < N) ? d_hA[(size_t)row * 9 + c] : 0.f;
    }
    __syncthreads();
    int col = tid & 127, half = tid >> 7;
    float s = 0.f, ss = 0.f;
    for (int r = half * 32; r < half * 32 + 32; r++) {
        int row = row0 + r;
        float acc = sb[col];
#pragma unroll
        for (int k = 0; k < 9; k++) acc = fmaf(sA[r * 9 + k], sW[k * 128 + col], acc);
        if (row < N) {
            d_hB[(size_t)row * 128 + col] = acc;
            s += acc;
            ss += acc * acc;
        }
    }
    atomicAdd(&sstat[col], s);
    atomicAdd(&sstat[128 + col], ss);
    __syncthreads();
    if (tid < 128) {
        atomicAdd(&d_stat[tid], sstat[tid]);
        atomicAdd(&d_stat[256 + tid], sstat[128 + tid]);
    }
}

// ---------------- weight pre-rounding ----------------
__global__ void k_roundW(const float* __restrict__ W, int n) {
    int i = blockIdx.x * blockDim.x + threadIdx.x;
    if (i < n) d_Wt[i] = f2tf_f(W[i]);
}

// ---------------- 3-stage pipelined TF32 GEMM, BK=32, fused stats ----------------
// C[N,M] = A[N,K] @ d_Wt[K,M] + bias.  A pre-rounded tf32. dynamic smem.
#define GEMM_STAGES 3
#define GEMM_ASTRIDE 36
#define GEMM_BSTRIDE 132
#define GEMM_SMEM (GEMM_STAGES * (128 * GEMM_ASTRIDE + 32 * GEMM_BSTRIDE) * 4)

__global__ void __launch_bounds__(256) k_gemm_tf32(int selA,
                                                   const float* __restrict__ bias,
                                                   float* Cext, int useExt, int doStats,
                                                   int N, int K, int M) {
    const float* A = selA ? d_pool : d_hA;
    float* C = useExt ? Cext : d_hB;
    extern __shared__ float smem[];
    float (*As)[128][GEMM_ASTRIDE] = (float (*)[128][GEMM_ASTRIDE])smem;
    float (*Bs)[32][GEMM_BSTRIDE] =
        (float (*)[32][GEMM_BSTRIDE])(smem + GEMM_STAGES * 128 * GEMM_ASTRIDE);
    __shared__ float sstat[256];

    int tid = threadIdx.x;
    int lane = tid & 31;
    int warp = tid >> 5;
    int wRow = warp & 1;
    int wCol = warp >> 1;
    int row0 = blockIdx.x * 128;
    int col0 = blockIdx.y * 128;
    int g = lane >> 2;
    int t4 = lane & 3;
    int nk = K >> 5;

    float acc[4][4][4];
#pragma unroll
    for (int mi = 0; mi < 4; mi++)
#pragma unroll
        for (int ni = 0; ni < 4; ni++)
#pragma unroll
            for (int r = 0; r < 4; r++) acc[mi][ni][r] = 0.f;

    auto prefetch = [&](int st, int k0) {
#pragma unroll
        for (int i = 0; i < 4; i++) {
            int idx = tid + i * 256;
            int r = idx >> 3, c4 = (idx & 7) << 2;
            const float* a = &A[(size_t)(row0 + r) * K + k0 * 32 + c4];
            cpa16(smem_u32(&As[st][r][c4]), a, row0 + r < N);
        }
#pragma unroll
        for (int i = 0; i < 4; i++) {
            int idx = tid + i * 256;
            int r = idx >> 5, c4 = (idx & 31) << 2;
            const float* b = &d_Wt[(size_t)(k0 * 32 + r) * M + col0 + c4];
            cpa16(smem_u32(&Bs[st][r][c4]), b, true);
        }
        cpa_commit();
    };

    prefetch(0, 0);
    if (nk > 1) prefetch(1, 1); else cpa_commit();

    for (int k0 = 0; k0 < nk; k0++) {
        cpa_wait<1>();
        __syncthreads();
        int st = k0 % GEMM_STAGES;
#pragma unroll
        for (int ks = 0; ks < 4; ks++) {
            int kk = ks * 8;
            unsigned af[4][4], bf[4][2];
#pragma unroll
            for (int mi = 0; mi < 4; mi++) {
                int rb = wRow * 64 + mi * 16;
                af[mi][0] = __float_as_uint(As[st][rb + g][kk + t4]);
                af[mi][1] = __float_as_uint(As[st][rb + 8 + g][kk + t4]);
                af[mi][2] = __float_as_uint(As[st][rb + g][kk + 4 + t4]);
                af[mi][3] = __float_as_uint(As[st][rb + 8 + g][kk + 4 + t4]);
            }
#pragma unroll
            for (int ni = 0; ni < 4; ni++) {
                int cb = wCol * 32 + ni * 8 + g;
                bf[ni][0] = __float_as_uint(Bs[st][kk + t4][cb]);
                bf[ni][1] = __float_as_uint(Bs[st][kk + 4 + t4][cb]);
            }
#pragma unroll
            for (int mi = 0; mi < 4; mi++)
#pragma unroll
                for (int ni = 0; ni < 4; ni++) mma_tf32(acc[mi][ni], af[mi], bf[ni]);
        }
        if (k0 + 2 < nk) prefetch((k0 + 2) % GEMM_STAGES, k0 + 2);
        else cpa_commit();
    }

    // epilogue: bias add + store (+ fused column stats)
    if (doStats) {
        sstat[tid] = 0.f;
        __syncthreads();
    }
#pragma unroll
    for (int mi = 0; mi < 4; mi++) {
#pragma unroll
        for (int ni = 0; ni < 4; ni++) {
            int row = row0 + wRow * 64 + mi * 16 + g;
            int colL = wCol * 32 + ni * 8 + t4 * 2;
            int col = col0 + colL;
            float b0 = bias[col], b1 = bias[col + 1];
            float v0 = acc[mi][ni][0] + b0, v1 = acc[mi][ni][1] + b1;
            float v2 = acc[mi][ni][2] + b0, v3 = acc[mi][ni][3] + b1;
            bool ok0 = row < N, ok1 = row + 8 < N;
            if (ok0) {
                C[(size_t)row * M + col] = v0;
                C[(size_t)row * M + col + 1] = v1;
            }
            if (ok1) {
                C[(size_t)(row + 8) * M + col] = v2;
                C[(size_t)(row + 8) * M + col + 1] = v3;
            }
            if (doStats) {
                float s0 = (ok0 ? v0 : 0.f) + (ok1 ? v2 : 0.f);
                float s1 = (ok0 ? v1 : 0.f) + (ok1 ? v3 : 0.f);
                float q0 = (ok0 ? v0 * v0 : 0.f) + (ok1 ? v2 * v2 : 0.f);
                float q1 = (ok0 ? v1 * v1 : 0.f) + (ok1 ? v3 * v3 : 0.f);
                atomicAdd(&sstat[colL], s0);
                atomicAdd(&sstat[colL + 1], s1);
                atomicAdd(&sstat[128 + colL], q0);
                atomicAdd(&sstat[128 + colL + 1], q1);
            }
        }
    }
    if (doStats) {
        __syncthreads();
        if (tid < 128) {
            atomicAdd(&d_stat[col0 + tid], sstat[tid]);
            atomicAdd(&d_stat[256 + col0 + tid], sstat[128 + tid]);
        }
    }
}

// ---------------- BN scale/shift (also zeroes stats for next layer) ----------
__global__ void k_scale_shift(const float* __restrict__ g, const float* __restrict__ be,
                              int N, int F) {
    int f = blockIdx.x * blockDim.x + threadIdx.x;
    if (f < F) {
        float inv_n = 1.f / (float)N;
        float mean = d_stat[f] * inv_n;
        float var = d_stat[256 + f] * inv_n - mean * mean;
        float sc = g[f] * rsqrtf(var + EPS_BN);
        d_stat[512 + f] = sc;
        d_stat[768 + f] = be[f] - mean * sc;
    }
    if (f < 256) {           // zero sum/sumsq for next layer
        d_stat[f] = 0.f;
        d_stat[256 + f] = 0.f;
    }
}

// ---------------- global mean pool (segmented, BN3+ReLU fused) ----------------
__global__ void k_zero_cnt(int G) {
    int i = blockIdx.x * blockDim.x + threadIdx.x;
    if (i < G) d_cnt[i] = 0u;
}
__global__ void k_cnt(int N) {
    int i = blockIdx.x * blockDim.x + threadIdx.x;
    if (i < N) atomicAdd(&d_cnt[d_batch32[i]], 1u);
}
__global__ void __launch_bounds__(256) k_pool2() {
    int gId = blockIdx.x;
    int f = threadIdx.x;
    int beg = d_goff[gId];
    int cnt = (int)d_cnt[gId];
    float sc = d_stat[512 + f], sh = d_stat[768 + f];
    float s = 0.f;
    for (int j = 0; j < cnt; j++) {
        float v = d_hB[(size_t)(beg + j) * 256 + f];
        s += fmaxf(fmaf(v, sc, sh), 0.f);
    }
    float inv = 1.f / (float)(cnt > 0 ? cnt : 1);
    d_pool[(size_t)gId * 256 + f] = f2tf_f(s * inv);
}

// ---------------- host driver ----------------
static inline int blk(int n, int t) { return (n + t - 1) / t; }

extern "C" void kernel_launch(void* const* d_in, const int* in_sizes, int n_in,
                              void* d_out, int out_size) {
    const float* x = (const float*)d_in[0];
    const void* ei = d_in[1];
    const void* batch = d_in[2];
    const int base = n_in - 14;
    const float* W1 = (const float*)d_in[base + 0];
    const float* b1 = (const float*)d_in[base + 1];
    const float* g1 = (const float*)d_in[base + 2];
    const float* be1 = (const float*)d_in[base + 3];
    const float* W2 = (const float*)d_in[base + 4];
    const float* b2 = (const float*)d_in[base + 5];
    const float* g2 = (const float*)d_in[base + 6];
    const float* be2 = (const float*)d_in[base + 7];
    const float* W3 = (const float*)d_in[base + 8];
    const float* b3 = (const float*)d_in[base + 9];
    const float* g3 = (const float*)d_in[base + 10];
    const float* be3 = (const float*)d_in[base + 11];
    const float* Wp = (const float*)d_in[base + 12];
    const float* bp = (const float*)d_in[base + 13];

    const int N = in_sizes[0] / 9;
    const int E = in_sizes[1] / 2;
    const int G = out_size / 256;
    const int T = 256;
    const int nb = blk(N, 256);
    const int nbg = blk(G, 256);

    cudaFuncSetAttribute(k_gemm_tf32, cudaFuncAttributeMaxDynamicSharedMemorySize,
                         GEMM_SMEM);

    // --- index conversion + degrees / norm ---
    k_sniff<<<1, 1>>>(ei);
    k_conv_ei<<<blk(2 * E, T), T>>>(ei, 2 * E);
    k_conv_batch<<<blk(N, T), T>>>(batch, N);
    k_count_deg<<<blk(E, T), T>>>(E);
    k_dis<<<blk(N, T), T>>>(N);

    // --- CSR by destination ---
    k_scan1<<<nb, 256>>>(N);
    k_scan2<<<1, 32>>>(nb);
    k_scan3<<<nb, 256>>>(N);
    k_fill<<<blk(E, T), T>>>(E);

    // --- layer 1: gather(x)[N,9] -> gemm 9->128 (stats fused) ---
    k_gather9<<<blk(N, T), T>>>(x, N);
    k_gemm1<<<blk(N, 64), 256>>>(W1, b1, N);
    k_scale_shift<<<1, 256>>>(g1, be1, N, 128);

    // --- layer 2: gather(BN1)[N,128] -> gemm 128->256 (stats fused) ---
    k_gather<<<blk(N, 8), 256>>>(N, 128);
    k_roundW<<<blk(128 * 256, T), T>>>(W2, 128 * 256);
    {
        dim3 grid(blk(N, 128), 2);
        k_gemm_tf32<<<grid, 256, GEMM_SMEM>>>(0, b2, nullptr, 0, 1, N, 128, 256);
    }
    k_scale_shift<<<1, 256>>>(g2, be2, N, 256);

    // --- layer 3: gather(BN2)[N,256] -> gemm 256->256 (stats fused) ---
    k_gather<<<blk(N, 8), 256>>>(N, 256);
    k_roundW<<<blk(256 * 256, T), T>>>(W3, 256 * 256);
    {
        dim3 grid(blk(N, 128), 2);
        k_gemm_tf32<<<grid, 256, GEMM_SMEM>>>(0, b3, nullptr, 0, 1, N, 256, 256);
    }
    k_scale_shift<<<1, 256>>>(g3, be3, N, 256);

    // --- segmented mean pool (BN3+ReLU fused, atomic-free) ---
    k_zero_cnt<<<nbg, 256>>>(G);
    k_cnt<<<blk(N, T), T>>>(N);
    k_gscan1<<<nbg, 256>>>(G);
    k_gscan2<<<1, 32>>>(nbg);
    k_gscan3<<<nbg, 256>>>(G);
    k_pool2<<<G, 256>>>();

    // --- final linear: d_out[G,256] = pooled @ Wp + bp ---
    k_roundW<<<blk(256 * 256, T), T>>>(Wp, 256 * 256);
    {
        dim3 grid(blk(G, 128), 2);
        k_gemm_tf32<<<grid, 256, GEMM_SMEM>>>(1, bp, (float*)d_out, 1, 0, G, 256, 256);
    }
}

// round 9
// speedup vs baseline: 1.0466x; 1.0466x over previous
#include <cuda_runtime.h>

// ---------------- static scratch (no allocation allowed) ----------------
#define NMAX 200000
#define EMAX 400000
#define FMAX 256
#define GMAX 8192
#define EPS_BN 1e-5f

__device__ float d_hA[(size_t)NMAX * FMAX];
__device__ float d_hB[(size_t)NMAX * FMAX];
__device__ float d_dis[NMAX];
__device__ unsigned int d_deg[NMAX];
__device__ float d_stat[4 * FMAX];
__device__ float d_pool[(size_t)GMAX * FMAX];
__device__ float d_Wt2[128 * 256];
__device__ float d_Wt3[256 * 256];
__device__ float d_Wtp[256 * 256];
__device__ unsigned int d_cnt[GMAX];
__device__ int d_goff[GMAX];
__device__ int d_ei32[2 * EMAX];
__device__ int d_batch32[NMAX];
__device__ int d_is64;
__device__ int d_off[NMAX];
__device__ unsigned int d_cur[NMAX];
__device__ int d_srcs[EMAX];
__device__ int d_bsum[1024];
__device__ int d_bsum2[64];

__device__ __forceinline__ float f2tf_f(float f) {
    unsigned r;
    asm("cvt.rna.tf32.f32 %0, %1;" : "=r"(r) : "f"(f));
    return __uint_as_float(r);
}
__device__ __forceinline__ unsigned smem_u32(const void* p) {
    return (unsigned)__cvta_generic_to_shared(p);
}
__device__ __forceinline__ void cpa16(unsigned dst, const void* src, bool pred) {
    int sz = pred ? 16 : 0;
    asm volatile("cp.async.ca.shared.global [%0], [%1], 16, %2;\n"
                 :: "r"(dst), "l"(src), "r"(sz));
}
__device__ __forceinline__ void cpa_commit() { asm volatile("cp.async.commit_group;\n"); }
template <int NWait>
__device__ __forceinline__ void cpa_wait() { asm volatile("cp.async.wait_group %0;\n" :: "n"(NWait)); }

__device__ __forceinline__ void mma_tf32(float* c, const unsigned* a, const unsigned* b) {
    asm volatile(
        "mma.sync.aligned.m16n8k8.row.col.f32.tf32.tf32.f32 "
        "{%0,%1,%2,%3}, {%4,%5,%6,%7}, {%8,%9}, {%0,%1,%2,%3};"
        : "+f"(c[0]), "+f"(c[1]), "+f"(c[2]), "+f"(c[3])
        : "r"(a[0]), "r"(a[1]), "r"(a[2]), "r"(a[3]), "r"(b[0]), "r"(b[1]));
}

__global__ void k_sniff(const void* ei) {
    const int* p = (const int*)ei;
    int ok64 = 1;
    for (int j = 0; j < 64; j++)
        if (p[2 * j + 1] != 0) ok64 = 0;
    d_is64 = ok64;
}
__global__ void k_conv_ei(const void* ei, int E2) {
    int i = blockIdx.x * blockDim.x + threadIdx.x;
    if (i < E2)
        d_ei32[i] = d_is64 ? (int)((const long long*)ei)[i] : ((const int*)ei)[i];
}
__global__ void k_conv_batch(const void* b, int N) {
    int i = blockIdx.x * blockDim.x + threadIdx.x;
    if (i < N) {
        d_batch32[i] = d_is64 ? (int)((const long long*)b)[i] : ((const int*)b)[i];
        d_deg[i] = 1u;
        d_cur[i] = 0u;
    }
    if (i < 512) d_stat[i] = 0.f;
}

// dst resolved IN DEVICE CODE (host must never touch __device__ symbols)
__global__ void k_roundW(const float* __restrict__ W, int sel, int n) {
    int i = blockIdx.x * blockDim.x + threadIdx.x;
    if (i < n) {
        float* dst = (sel == 0) ? d_Wt2 : (sel == 1 ? d_Wt3 : d_Wtp);
        dst[i] = f2tf_f(W[i]);
    }
}

__global__ void k_count_deg(int E) {
    int e = blockIdx.x * blockDim.x + threadIdx.x;
    if (e < E) atomicAdd(&d_deg[d_ei32[E + e]], 1u);
}
__global__ void k_dis(int N) {
    int i = blockIdx.x * blockDim.x + threadIdx.x;
    if (i < N) d_dis[i] = rsqrtf((float)d_deg[i]);
}

__global__ void k_scan1(int N) {
    __shared__ int sh[256];
    int i = blockIdx.x * 256 + threadIdx.x;
    int v = (i < N) ? (int)d_deg[i] - 1 : 0;
    sh[threadIdx.x] = v;
    __syncthreads();
    for (int o = 128; o > 0; o >>= 1) {
        if (threadIdx.x < o) sh[threadIdx.x] += sh[threadIdx.x + o];
        __syncthreads();
    }
    if (threadIdx.x == 0) d_bsum[blockIdx.x] = sh[0];
}
__global__ void k_scan2(int nb) {
    if (threadIdx.x == 0 && blockIdx.x == 0) {
        int run = 0;
        for (int b = 0; b < nb; b++) { int t = d_bsum[b]; d_bsum[b] = run; run += t; }
    }
}
__global__ void k_scan3(int N) {
    __shared__ int sh[256];
    int i = blockIdx.x * 256 + threadIdx.x;
    int v = (i < N) ? (int)d_deg[i] - 1 : 0;
    sh[threadIdx.x] = v;
    __syncthreads();
    for (int o = 1; o < 256; o <<= 1) {
        int t = (threadIdx.x >= o) ? sh[threadIdx.x - o] : 0;
        __syncthreads();
        sh[threadIdx.x] += t;
        __syncthreads();
    }
    if (i < N) d_off[i] = d_bsum[blockIdx.x] + sh[threadIdx.x] - v;
}
__global__ void k_fill(int E) {
    int e = blockIdx.x * blockDim.x + threadIdx.x;
    if (e < E) {
        int s = d_ei32[e], d = d_ei32[E + e];
        int pos = d_off[d] + (int)atomicAdd(&d_cur[d], 1u);
        d_srcs[pos] = s;
    }
}

__global__ void k_gscan1(int G) {
    __shared__ int sh[256];
    int i = blockIdx.x * 256 + threadIdx.x;
    int v = (i < G) ? (int)d_cnt[i] : 0;
    sh[threadIdx.x] = v;
    __syncthreads();
    for (int o = 128; o > 0; o >>= 1) {
        if (threadIdx.x < o) sh[threadIdx.x] += sh[threadIdx.x + o];
        __syncthreads();
    }
    if (threadIdx.x == 0) d_bsum2[blockIdx.x] = sh[0];
}
__global__ void k_gscan2(int nb) {
    if (threadIdx.x == 0 && blockIdx.x == 0) {
        int run = 0;
        for (int b = 0; b < nb; b++) { int t = d_bsum2[b]; d_bsum2[b] = run; run += t; }
    }
}
__global__ void k_gscan3(int G) {
    __shared__ int sh[256];
    int i = blockIdx.x * 256 + threadIdx.x;
    int v = (i < G) ? (int)d_cnt[i] : 0;
    sh[threadIdx.x] = v;
    __syncthreads();
    for (int o = 1; o < 256; o <<= 1) {
        int t = (threadIdx.x >= o) ? sh[threadIdx.x - o] : 0;
        __syncthreads();
        sh[threadIdx.x] += t;
        __syncthreads();
    }
    if (i < G) d_goff[i] = d_bsum2[blockIdx.x] + sh[threadIdx.x] - v;
}

__global__ void k_gather9(const float* __restrict__ x, int N) {
    int i = blockIdx.x * blockDim.x + threadIdx.x;
    if (i >= N) return;
    float di = d_dis[i];
    float acc[9];
    const float* xi = x + (size_t)i * 9;
#pragma unroll
    for (int f = 0; f < 9; f++) acc[f] = di * di * xi[f];
    int beg = d_off[i], cnt = (int)d_deg[i] - 1;
    for (int j = 0; j < cnt; j++) {
        int s = d_srcs[beg + j];
        float w = d_dis[s] * di;
        const float* xs = x + (size_t)s * 9;
#pragma unroll
        for (int f = 0; f < 9; f++) acc[f] += w * xs[f];
    }
    float* o = d_hA + (size_t)i * 9;
#pragma unroll
    for (int f = 0; f < 9; f++) o[f] = acc[f];
}
__global__ void k_gather(int N, int F) {
    int w = (blockIdx.x * blockDim.x + threadIdx.x) >> 5;
    int lane = threadIdx.x & 31;
    if (w >= N) return;
    int C4 = F >> 7;
    float di = d_dis[w];
    float4 sc[2], sh[2], acc[2];
#pragma unroll
    for (int c = 0; c < 2; c++) {
        if (c < C4) {
            int col = c * 128 + lane * 4;
            sc[c] = *(const float4*)&d_stat[512 + col];
            sh[c] = *(const float4*)&d_stat[768 + col];
        }
    }
    {
        float ww = di * di;
        const float4* row = (const float4*)(d_hB + (size_t)w * F);
#pragma unroll
        for (int c = 0; c < 2; c++) {
            if (c < C4) {
                float4 v = row[c * 32 + lane];
                acc[c].x = ww * fmaxf(fmaf(v.x, sc[c].x, sh[c].x), 0.f);
                acc[c].y = ww * fmaxf(fmaf(v.y, sc[c].y, sh[c].y), 0.f);
                acc[c].z = ww * fmaxf(fmaf(v.z, sc[c].z, sh[c].z), 0.f);
                acc[c].w = ww * fmaxf(fmaf(v.w, sc[c].w, sh[c].w), 0.f);
            }
        }
    }
    int beg = d_off[w], cnt = (int)d_deg[w] - 1;
    for (int j = 0; j < cnt; j++) {
        int s = d_srcs[beg + j];
        float we = d_dis[s] * di;
        const float4* row = (const float4*)(d_hB + (size_t)s * F);
#pragma unroll
        for (int c = 0; c < 2; c++) {
            if (c < C4) {
                float4 v = row[c * 32 + lane];
                acc[c].x = fmaf(we, fmaxf(fmaf(v.x, sc[c].x, sh[c].x), 0.f), acc[c].x);
                acc[c].y = fmaf(we, fmaxf(fmaf(v.y, sc[c].y, sh[c].y), 0.f), acc[c].y);
                acc[c].z = fmaf(we, fmaxf(fmaf(v.z, sc[c].z, sh[c].z), 0.f), acc[c].z);
                acc[c].w = fmaf(we, fmaxf(fmaf(v.w, sc[c].w, sh[c].w), 0.f), acc[c].w);
            }
        }
    }
    float4* o = (float4*)(d_hA + (size_t)w * F);
#pragma unroll
    for (int c = 0; c < 2; c++) {
        if (c < C4) {
            float4 r;
            r.x = f2tf_f(acc[c].x); r.y = f2tf_f(acc[c].y);
            r.z = f2tf_f(acc[c].z); r.w = f2tf_f(acc[c].w);
            o[c * 32 + lane] = r;
        }
    }
}

__global__ void __launch_bounds__(256) k_gemm1(const float* __restrict__ W,
                                               const float* __restrict__ b, int N) {
    __shared__ float sW[9 * 128];
    __shared__ float sb[128];
    __shared__ float sA[64 * 9];
    __shared__ float sstat[256];
    int tid = threadIdx.x;
    for (int i = tid; i < 9 * 128; i += 256) sW[i] = W[i];
    if (tid < 128) sb[tid] = b[tid];
    sstat[tid] = 0.f;
    int row0 = blockIdx.x * 64;
    for (int i = tid; i < 576; i += 256) {
        int r = i / 9, c = i - r * 9;
        int row = row0 + r;
        sA[i] = (row < N) ? d_hA[(size_t)row * 9 + c] : 0.f;
    }
    __syncthreads();
    int col = tid & 127, half = tid >> 7;
    float s = 0.f, ss = 0.f;
    for (int r = half * 32; r < half * 32 + 32; r++) {
        int row = row0 + r;
        float acc = sb[col];
#pragma unroll
        for (int k = 0; k < 9; k++) acc = fmaf(sA[r * 9 + k], sW[k * 128 + col], acc);
        if (row < N) {
            d_hB[(size_t)row * 128 + col] = acc;
            s += acc;
            ss += acc * acc;
        }
    }
    atomicAdd(&sstat[col], s);
    atomicAdd(&sstat[128 + col], ss);
    __syncthreads();
    if (tid < 128) {
        atomicAdd(&d_stat[tid], sstat[tid]);
        atomicAdd(&d_stat[256 + tid], sstat[128 + tid]);
    }
}

__global__ void __launch_bounds__(256) k_gemm_tf32(int selA, int selB,
                                                   const float* __restrict__ bias,
                                                   float* Cext, int useExt, int doStats,
                                                   int N, int K, int M) {
    const float* A = selA ? d_pool : d_hA;
    const float* Wt = (selB == 0) ? d_Wt2 : (selB == 1 ? d_Wt3 : d_Wtp);
    float* C = useExt ? Cext : d_hB;
    __shared__ __align__(16) float As[2][128][20];
    __shared__ __align__(16) float Bs[2][16][136];
    __shared__ float sstat[256];

    int tid = threadIdx.x;
    int lane = tid & 31;
    int warp = tid >> 5;
    int wRow = warp & 1;
    int wCol = warp >> 1;
    int row0 = blockIdx.x * 128;
    int col0 = blockIdx.y * 128;
    int g = lane >> 2;
    int t4 = lane & 3;
    int nk = K >> 4;

    float acc[4][4][4];
#pragma unroll
    for (int mi = 0; mi < 4; mi++)
#pragma unroll
        for (int ni = 0; ni < 4; ni++)
#pragma unroll
            for (int r = 0; r < 4; r++) acc[mi][ni][r] = 0.f;

    int rA0 = tid >> 2, cA0 = (tid & 3) << 2;
    int rA1 = (tid + 256) >> 2, cA1 = cA0;
    int rB0 = tid >> 5, cB0 = (tid & 31) << 2;
    int rB1 = rB0 + 8, cB1 = cB0;

    auto prefetch = [&](int st, int k0) {
        const float* a0 = &A[(size_t)(row0 + rA0) * K + k0 * 16 + cA0];
        const float* a1 = &A[(size_t)(row0 + rA1) * K + k0 * 16 + cA1];
        cpa16(smem_u32(&As[st][rA0][cA0]), a0, row0 + rA0 < N);
        cpa16(smem_u32(&As[st][rA1][cA1]), a1, row0 + rA1 < N);
        const float* b0 = &Wt[(size_t)(k0 * 16 + rB0) * M + col0 + cB0];
        const float* b1 = &Wt[(size_t)(k0 * 16 + rB1) * M + col0 + cB1];
        cpa16(smem_u32(&Bs[st][rB0][cB0]), b0, true);
        cpa16(smem_u32(&Bs[st][rB1][cB1]), b1, true);
        cpa_commit();
    };

    prefetch(0, 0);
    for (int k0 = 0; k0 < nk; k0++) {
        if (k0 + 1 < nk) prefetch((k0 + 1) & 1, k0 + 1);
        else cpa_commit();
        cpa_wait<1>();
        __syncthreads();
        int st = k0 & 1;
#pragma unroll
        for (int ks = 0; ks < 2; ks++) {
            int kk = ks * 8;
            unsigned af[4][4], bf[4][2];
#pragma unroll
            for (int mi = 0; mi < 4; mi++) {
                int rb = wRow * 64 + mi * 16;
                af[mi][0] = __float_as_uint(As[st][rb + g][kk + t4]);
                af[mi][1] = __float_as_uint(As[st][rb + 8 + g][kk + t4]);
                af[mi][2] = __float_as_uint(As[st][rb + g][kk + 4 + t4]);
                af[mi][3] = __float_as_uint(As[st][rb + 8 + g][kk + 4 + t4]);
            }
#pragma unroll
            for (int ni = 0; ni < 4; ni++) {
                int cb = wCol * 32 + ni * 8 + g;
                bf[ni][0] = __float_as_uint(Bs[st][kk + t4][cb]);
                bf[ni][1] = __float_as_uint(Bs[st][kk + 4 + t4][cb]);
            }
#pragma unroll
            for (int mi = 0; mi < 4; mi++)
#pragma unroll
                for (int ni = 0; ni < 4; ni++) mma_tf32(acc[mi][ni], af[mi], bf[ni]);
        }
        __syncthreads();
    }

    if (doStats) {
        sstat[tid] = 0.f;
        __syncthreads();
    }
#pragma unroll
    for (int mi = 0; mi < 4; mi++) {
#pragma unroll
        for (int ni = 0; ni < 4; ni++) {
            int row = row0 + wRow * 64 + mi * 16 + g;
            int colL = wCol * 32 + ni * 8 + t4 * 2;
            int col = col0 + colL;
            float b0 = bias[col], b1 = bias[col + 1];
            float v0 = acc[mi][ni][0] + b0, v1 = acc[mi][ni][1] + b1;
            float v2 = acc[mi][ni][2] + b0, v3 = acc[mi][ni][3] + b1;
            bool ok0 = row < N, ok1 = row + 8 < N;
            if (ok0) {
                C[(size_t)row * M + col] = v0;
                C[(size_t)row * M + col + 1] = v1;
            }
            if (ok1) {
                C[(size_t)(row + 8) * M + col] = v2;
                C[(size_t)(row + 8) * M + col + 1] = v3;
            }
            if (doStats) {
                float s0 = (ok0 ? v0 : 0.f) + (ok1 ? v2 : 0.f);
                float s1 = (ok0 ? v1 : 0.f) + (ok1 ? v3 : 0.f);
                float q0 = (ok0 ? v0 * v0 : 0.f) + (ok1 ? v2 * v2 : 0.f);
                float q1 = (ok0 ? v1 * v1 : 0.f) + (ok1 ? v3 * v3 : 0.f);
                atomicAdd(&sstat[colL], s0);
                atomicAdd(&sstat[colL + 1], s1);
                atomicAdd(&sstat[128 + colL], q0);
                atomicAdd(&sstat[128 + colL + 1], q1);
            }
        }
    }
    if (doStats) {
        __syncthreads();
        if (tid < 128) {
            atomicAdd(&d_stat[col0 + tid], sstat[tid]);
            atomicAdd(&d_stat[256 + col0 + tid], sstat[128 + tid]);
        }
    }
}

__global__ void k_scale_shift(const float* __restrict__ g, const float* __restrict__ be,
                              int N, int F) {
    int f = blockIdx.x * blockDim.x + threadIdx.x;
    if (f < F) {
        float inv_n = 1.f / (float)N;
        float mean = d_stat[f] * inv_n;
        float var = d_stat[256 + f] * inv_n - mean * mean;
        float sc = g[f] * rsqrtf(var + EPS_BN);
        d_stat[512 + f] = sc;
        d_stat[768 + f] = be[f] - mean * sc;
    }
    if (f < 256) {
        d_stat[f] = 0.f;
        d_stat[256 + f] = 0.f;
    }
}

__global__ void k_zero_cnt(int G) {
    int i = blockIdx.x * blockDim.x + threadIdx.x;
    if (i < G) d_cnt[i] = 0u;
}
__global__ void k_cnt(int N) {
    int i = blockIdx.x * blockDim.x + threadIdx.x;
    if (i < N) atomicAdd(&d_cnt[d_batch32[i]], 1u);
}
__global__ void __launch_bounds__(256) k_pool2() {
    int gId = blockIdx.x;
    int f = threadIdx.x;
    int beg = d_goff[gId];
    int cnt = (int)d_cnt[gId];
    float sc = d_stat[512 + f], sh = d_stat[768 + f];
    float s = 0.f;
    for (int j = 0; j < cnt; j++) {
        float v = d_hB[(size_t)(beg + j) * 256 + f];
        s += fmaxf(fmaf(v, sc, sh), 0.f);
    }
    float inv = 1.f / (float)(cnt > 0 ? cnt : 1);
    d_pool[(size_t)gId * 256 + f] = f2tf_f(s * inv);
}

static inline int blk(int n, int t) { return (n + t - 1) / t; }

extern "C" void kernel_launch(void* const* d_in, const int* in_sizes, int n_in,
                              void* d_out, int out_size) {
    const float* x = (const float*)d_in[0];
    const void* ei = d_in[1];
    const void* batch = d_in[2];
    const int base = n_in - 14;
    const float* W1 = (const float*)d_in[base + 0];
    const float* b1 = (const float*)d_in[base + 1];
    const float* g1 = (const float*)d_in[base + 2];
    const float* be1 = (const float*)d_in[base + 3];
    const float* W2 = (const float*)d_in[base + 4];
    const float* b2 = (const float*)d_in[base + 5];
    const float* g2 = (const float*)d_in[base + 6];
    const float* be2 = (const float*)d_in[base + 7];
    const float* W3 = (const float*)d_in[base + 8];
    const float* b3 = (const float*)d_in[base + 9];
    const float* g3 = (const float*)d_in[base + 10];
    const float* be3 = (const float*)d_in[base + 11];
    const float* Wp = (const float*)d_in[base + 12];
    const float* bp = (const float*)d_in[base + 13];

    const int N = in_sizes[0] / 9;
    const int E = in_sizes[1] / 2;
    const int G = out_size / 256;
    const int T = 256;
    const int nb = blk(N, 256);
    const int nbg = blk(G, 256);

    // --- weight pre-rounding (dst selected device-side) ---
    k_roundW<<<blk(128 * 256, T), T>>>(W2, 0, 128 * 256);
    k_roundW<<<blk(256 * 256, T), T>>>(W3, 1, 256 * 256);
    k_roundW<<<blk(256 * 256, T), T>>>(Wp, 2, 256 * 256);

    // --- index conversion + degrees / norm ---
    k_sniff<<<1, 1>>>(ei);
    k_conv_ei<<<blk(2 * E, T), T>>>(ei, 2 * E);
    k_conv_batch<<<blk(N, T), T>>>(batch, N);
    k_count_deg<<<blk(E, T), T>>>(E);
    k_dis<<<blk(N, T), T>>>(N);

    // --- CSR by destination ---
    k_scan1<<<nb, 256>>>(N);
    k_scan2<<<1, 32>>>(nb);
    k_scan3<<<nb, 256>>>(N);
    k_fill<<<blk(E, T), T>>>(E);

    // --- layer 1 ---
    k_gather9<<<blk(N, T), T>>>(x, N);
    k_gemm1<<<blk(N, 64), 256>>>(W1, b1, N);
    k_scale_shift<<<1, 256>>>(g1, be1, N, 128);

    // --- layer 2 ---
    k_gather<<<blk(N, 8), 256>>>(N, 128);
    {
        dim3 grid(blk(N, 128), 2);
        k_gemm_tf32<<<grid, 256>>>(0, 0, b2, nullptr, 0, 1, N, 128, 256);
    }
    k_scale_shift<<<1, 256>>>(g2, be2, N, 256);

    // --- layer 3 ---
    k_gather<<<blk(N, 8), 256>>>(N, 256);
    {
        dim3 grid(blk(N, 128), 2);
        k_gemm_tf32<<<grid, 256>>>(0, 1, b3, nullptr, 0, 1, N, 256, 256);
    }
    k_scale_shift<<<1, 256>>>(g3, be3, N, 256);

    // --- segmented mean pool ---
    k_zero_cnt<<<nbg, 256>>>(G);
    k_cnt<<<blk(N, T), T>>>(N);
    k_gscan1<<<nbg, 256>>>(G);
    k_gscan2<<<1, 32>>>(nbg);
    k_gscan3<<<nbg, 256>>>(G);
    k_pool2<<<G, 256>>>();

    // --- final linear ---
    {
        dim3 grid(blk(G, 128), 2);
        k_gemm_tf32<<<grid, 256>>>(1, 2, bp, (float*)d_out, 1, 0, G, 256, 256);
    }
}

// round 10
// speedup vs baseline: 1.0651x; 1.0177x over previous
#include <cuda_runtime.h>

// ---------------- static scratch (no allocation allowed) ----------------
#define NMAX 200000
#define EMAX 400000
#define FMAX 256
#define GMAX 8192
#define EPS_BN 1e-5f

__device__ float d_hA[(size_t)NMAX * FMAX];
__device__ float d_hB[(size_t)NMAX * FMAX];
__device__ float d_dis[NMAX];
__device__ unsigned int d_deg[NMAX];
__device__ float d_stat[4 * FMAX];
__device__ float d_pool[(size_t)GMAX * FMAX];
__device__ float d_Wt2[128 * 256];
__device__ float d_Wt3[256 * 256];
__device__ float d_Wtp[256 * 256];
__device__ unsigned int d_cnt[GMAX];
__device__ int d_goff[GMAX];
__device__ int d_ei32[2 * EMAX];
__device__ int d_batch32[NMAX];
__device__ int d_is64;
__device__ int d_off[NMAX];
__device__ unsigned int d_cur[NMAX];
__device__ int d_srcs[EMAX];
__device__ int d_bsum[1024];
__device__ int d_bsum2[64];

__device__ __forceinline__ float f2tf_f(float f) {
    unsigned r;
    asm("cvt.rna.tf32.f32 %0, %1;" : "=r"(r) : "f"(f));
    return __uint_as_float(r);
}
__device__ __forceinline__ unsigned smem_u32(const void* p) {
    return (unsigned)__cvta_generic_to_shared(p);
}
__device__ __forceinline__ void cpa16(unsigned dst, const void* src, bool pred) {
    int sz = pred ? 16 : 0;
    asm volatile("cp.async.ca.shared.global [%0], [%1], 16, %2;\n"
                 :: "r"(dst), "l"(src), "r"(sz));
}
__device__ __forceinline__ void cpa_commit() { asm volatile("cp.async.commit_group;\n"); }
template <int NWait>
__device__ __forceinline__ void cpa_wait() { asm volatile("cp.async.wait_group %0;\n" :: "n"(NWait)); }

__device__ __forceinline__ void mma_tf32(float* c, const unsigned* a, const unsigned* b) {
    asm volatile(
        "mma.sync.aligned.m16n8k8.row.col.f32.tf32.tf32.f32 "
        "{%0,%1,%2,%3}, {%4,%5,%6,%7}, {%8,%9}, {%0,%1,%2,%3};"
        : "+f"(c[0]), "+f"(c[1]), "+f"(c[2]), "+f"(c[3])
        : "r"(a[0]), "r"(a[1]), "r"(a[2]), "r"(a[3]), "r"(b[0]), "r"(b[1]));
}

__global__ void k_sniff(const void* ei) {
    const int* p = (const int*)ei;
    int ok64 = 1;
    for (int j = 0; j < 64; j++)
        if (p[2 * j + 1] != 0) ok64 = 0;
    d_is64 = ok64;
}
__global__ void k_conv_ei(const void* ei, int E2) {
    int i = blockIdx.x * blockDim.x + threadIdx.x;
    if (i < E2)
        d_ei32[i] = d_is64 ? (int)((const long long*)ei)[i] : ((const int*)ei)[i];
}
__global__ void k_conv_batch(const void* b, int N) {
    int i = blockIdx.x * blockDim.x + threadIdx.x;
    if (i < N) {
        d_batch32[i] = d_is64 ? (int)((const long long*)b)[i] : ((const int*)b)[i];
        d_deg[i] = 1u;
        d_cur[i] = 0u;
    }
    if (i < 512) d_stat[i] = 0.f;
}

// dst resolved IN DEVICE CODE (host must never touch __device__ symbols)
__global__ void k_roundW(const float* __restrict__ W, int sel, int n) {
    int i = blockIdx.x * blockDim.x + threadIdx.x;
    if (i < n) {
        float* dst = (sel == 0) ? d_Wt2 : (sel == 1 ? d_Wt3 : d_Wtp);
        dst[i] = f2tf_f(W[i]);
    }
}

__global__ void k_count_deg(int E) {
    int e = blockIdx.x * blockDim.x + threadIdx.x;
    if (e < E) atomicAdd(&d_deg[d_ei32[E + e]], 1u);
}
__global__ void k_dis(int N) {
    int i = blockIdx.x * blockDim.x + threadIdx.x;
    if (i < N) d_dis[i] = rsqrtf((float)d_deg[i]);
}

__global__ void k_scan1(int N) {
    __shared__ int sh[256];
    int i = blockIdx.x * 256 + threadIdx.x;
    int v = (i < N) ? (int)d_deg[i] - 1 : 0;
    sh[threadIdx.x] = v;
    __syncthreads();
    for (int o = 128; o > 0; o >>= 1) {
        if (threadIdx.x < o) sh[threadIdx.x] += sh[threadIdx.x + o];
        __syncthreads();
    }
    if (threadIdx.x == 0) d_bsum[blockIdx.x] = sh[0];
}
__global__ void k_scan2(int nb) {
    if (threadIdx.x == 0 && blockIdx.x == 0) {
        int run = 0;
        for (int b = 0; b < nb; b++) { int t = d_bsum[b]; d_bsum[b] = run; run += t; }
    }
}
__global__ void k_scan3(int N) {
    __shared__ int sh[256];
    int i = blockIdx.x * 256 + threadIdx.x;
    int v = (i < N) ? (int)d_deg[i] - 1 : 0;
    sh[threadIdx.x] = v;
    __syncthreads();
    for (int o = 1; o < 256; o <<= 1) {
        int t = (threadIdx.x >= o) ? sh[threadIdx.x - o] : 0;
        __syncthreads();
        sh[threadIdx.x] += t;
        __syncthreads();
    }
    if (i < N) d_off[i] = d_bsum[blockIdx.x] + sh[threadIdx.x] - v;
}
__global__ void k_fill(int E) {
    int e = blockIdx.x * blockDim.x + threadIdx.x;
    if (e < E) {
        int s = d_ei32[e], d = d_ei32[E + e];
        int pos = d_off[d] + (int)atomicAdd(&d_cur[d], 1u);
        d_srcs[pos] = s;
    }
}

__global__ void k_gscan1(int G) {
    __shared__ int sh[256];
    int i = blockIdx.x * 256 + threadIdx.x;
    int v = (i < G) ? (int)d_cnt[i] : 0;
    sh[threadIdx.x] = v;
    __syncthreads();
    for (int o = 128; o > 0; o >>= 1) {
        if (threadIdx.x < o) sh[threadIdx.x] += sh[threadIdx.x + o];
        __syncthreads();
    }
    if (threadIdx.x == 0) d_bsum2[blockIdx.x] = sh[0];
}
__global__ void k_gscan2(int nb) {
    if (threadIdx.x == 0 && blockIdx.x == 0) {
        int run = 0;
        for (int b = 0; b < nb; b++) { int t = d_bsum2[b]; d_bsum2[b] = run; run += t; }
    }
}
__global__ void k_gscan3(int G) {
    __shared__ int sh[256];
    int i = blockIdx.x * 256 + threadIdx.x;
    int v = (i < G) ? (int)d_cnt[i] : 0;
    sh[threadIdx.x] = v;
    __syncthreads();
    for (int o = 1; o < 256; o <<= 1) {
        int t = (threadIdx.x >= o) ? sh[threadIdx.x - o] : 0;
        __syncthreads();
        sh[threadIdx.x] += t;
        __syncthreads();
    }
    if (i < G) d_goff[i] = d_bsum2[blockIdx.x] + sh[threadIdx.x] - v;
}

__global__ void k_gather9(const float* __restrict__ x, int N) {
    int i = blockIdx.x * blockDim.x + threadIdx.x;
    if (i >= N) return;
    float di = d_dis[i];
    float acc[9];
    const float* xi = x + (size_t)i * 9;
#pragma unroll
    for (int f = 0; f < 9; f++) acc[f] = di * di * xi[f];
    int beg = d_off[i], cnt = (int)d_deg[i] - 1;
    for (int j = 0; j < cnt; j++) {
        int s = d_srcs[beg + j];
        float w = d_dis[s] * di;
        const float* xs = x + (size_t)s * 9;
#pragma unroll
        for (int f = 0; f < 9; f++) acc[f] += w * xs[f];
    }
    float* o = d_hA + (size_t)i * 9;
#pragma unroll
    for (int f = 0; f < 9; f++) o[f] = acc[f];
}
__global__ void k_gather(int N, int F) {
    int w = (blockIdx.x * blockDim.x + threadIdx.x) >> 5;
    int lane = threadIdx.x & 31;
    if (w >= N) return;
    int C4 = F >> 7;
    float di = d_dis[w];
    float4 sc[2], sh[2], acc[2];
#pragma unroll
    for (int c = 0; c < 2; c++) {
        if (c < C4) {
            int col = c * 128 + lane * 4;
            sc[c] = *(const float4*)&d_stat[512 + col];
            sh[c] = *(const float4*)&d_stat[768 + col];
        }
    }
    {
        float ww = di * di;
        const float4* row = (const float4*)(d_hB + (size_t)w * F);
#pragma unroll
        for (int c = 0; c < 2; c++) {
            if (c < C4) {
                float4 v = row[c * 32 + lane];
                acc[c].x = ww * fmaxf(fmaf(v.x, sc[c].x, sh[c].x), 0.f);
                acc[c].y = ww * fmaxf(fmaf(v.y, sc[c].y, sh[c].y), 0.f);
                acc[c].z = ww * fmaxf(fmaf(v.z, sc[c].z, sh[c].z), 0.f);
                acc[c].w = ww * fmaxf(fmaf(v.w, sc[c].w, sh[c].w), 0.f);
            }
        }
    }
    int beg = d_off[w], cnt = (int)d_deg[w] - 1;
    for (int j = 0; j < cnt; j++) {
        int s = d_srcs[beg + j];
        float we = d_dis[s] * di;
        const float4* row = (const float4*)(d_hB + (size_t)s * F);
#pragma unroll
        for (int c = 0; c < 2; c++) {
            if (c < C4) {
                float4 v = row[c * 32 + lane];
                acc[c].x = fmaf(we, fmaxf(fmaf(v.x, sc[c].x, sh[c].x), 0.f), acc[c].x);
                acc[c].y = fmaf(we, fmaxf(fmaf(v.y, sc[c].y, sh[c].y), 0.f), acc[c].y);
                acc[c].z = fmaf(we, fmaxf(fmaf(v.z, sc[c].z, sh[c].z), 0.f), acc[c].z);
                acc[c].w = fmaf(we, fmaxf(fmaf(v.w, sc[c].w, sh[c].w), 0.f), acc[c].w);
            }
        }
    }
    float4* o = (float4*)(d_hA + (size_t)w * F);
#pragma unroll
    for (int c = 0; c < 2; c++) {
        if (c < C4) {
            float4 r;
            r.x = f2tf_f(acc[c].x); r.y = f2tf_f(acc[c].y);
            r.z = f2tf_f(acc[c].z); r.w = f2tf_f(acc[c].w);
            o[c * 32 + lane] = r;
        }
    }
}

__global__ void __launch_bounds__(256) k_gemm1(const float* __restrict__ W,
                                               const float* __restrict__ b, int N) {
    __shared__ float sW[9 * 128];
    __shared__ float sb[128];
    __shared__ float sA[64 * 9];
    __shared__ float sstat[256];
    int tid = threadIdx.x;
    for (int i = tid; i < 9 * 128; i += 256) sW[i] = W[i];
    if (tid < 128) sb[tid] = b[tid];
    sstat[tid] = 0.f;
    int row0 = blockIdx.x * 64;
    for (int i = tid; i < 576; i += 256) {
        int r = i / 9, c = i - r * 9;
        int row = row0 + r;
        sA[i] = (row < N) ? d_hA[(size_t)row * 9 + c] : 0.f;
    }
    __syncthreads();
    int col = tid & 127, half = tid >> 7;
    float s = 0.f, ss = 0.f;
    for (int r = half * 32; r < half * 32 + 32; r++) {
        int row = row0 + r;
        float acc = sb[col];
#pragma unroll
        for (int k = 0; k < 9; k++) acc = fmaf(sA[r * 9 + k], sW[k * 128 + col], acc);
        if (row < N) {
            d_hB[(size_t)row * 128 + col] = acc;
            s += acc;
            ss += acc * acc;
        }
    }
    atomicAdd(&sstat[col], s);
    atomicAdd(&sstat[128 + col], ss);
    __syncthreads();
    if (tid < 128) {
        atomicAdd(&d_stat[tid], sstat[tid]);
        atomicAdd(&d_stat[256 + tid], sstat[128 + tid]);
    }
}

// ---------------- 3-stage pipelined TF32 GEMM, BK=16, single sync/iter ------
#define GEMM_STAGES 3
#define ASTR 20
#define BSTR 136
#define GEMM_SMEM (GEMM_STAGES * (128 * ASTR + 16 * BSTR) * 4)

__global__ void __launch_bounds__(256) k_gemm_tf32(int selA, int selB,
                                                   const float* __restrict__ bias,
                                                   float* Cext, int useExt, int doStats,
                                                   int N, int K, int M) {
    const float* A = selA ? d_pool : d_hA;
    const float* Wt = (selB == 0) ? d_Wt2 : (selB == 1 ? d_Wt3 : d_Wtp);
    float* C = useExt ? Cext : d_hB;
    extern __shared__ float smem[];
    float (*As)[128][ASTR] = (float (*)[128][ASTR])smem;
    float (*Bs)[16][BSTR] = (float (*)[16][BSTR])(smem + GEMM_STAGES * 128 * ASTR);
    __shared__ float sstat[256];

    int tid = threadIdx.x;
    int lane = tid & 31;
    int warp = tid >> 5;
    int wRow = warp & 1;
    int wCol = warp >> 1;
    int row0 = blockIdx.x * 128;
    int col0 = blockIdx.y * 128;
    int g = lane >> 2;
    int t4 = lane & 3;
    int nk = K >> 4;

    float acc[4][4][4];
#pragma unroll
    for (int mi = 0; mi < 4; mi++)
#pragma unroll
        for (int ni = 0; ni < 4; ni++)
#pragma unroll
            for (int r = 0; r < 4; r++) acc[mi][ni][r] = 0.f;

    int rA0 = tid >> 2, cA0 = (tid & 3) << 2;
    int rA1 = (tid + 256) >> 2, cA1 = cA0;
    int rB0 = tid >> 5, cB0 = (tid & 31) << 2;
    int rB1 = rB0 + 8, cB1 = cB0;

    auto prefetch = [&](int st, int k0) {
        const float* a0 = &A[(size_t)(row0 + rA0) * K + k0 * 16 + cA0];
        const float* a1 = &A[(size_t)(row0 + rA1) * K + k0 * 16 + cA1];
        cpa16(smem_u32(&As[st][rA0][cA0]), a0, row0 + rA0 < N);
        cpa16(smem_u32(&As[st][rA1][cA1]), a1, row0 + rA1 < N);
        const float* b0 = &Wt[(size_t)(k0 * 16 + rB0) * M + col0 + cB0];
        const float* b1 = &Wt[(size_t)(k0 * 16 + rB1) * M + col0 + cB1];
        cpa16(smem_u32(&Bs[st][rB0][cB0]), b0, true);
        cpa16(smem_u32(&Bs[st][rB1][cB1]), b1, true);
        cpa_commit();
    };

    prefetch(0, 0);
    if (nk > 1) prefetch(1, 1); else cpa_commit();

    for (int k0 = 0; k0 < nk; k0++) {
        cpa_wait<1>();           // stage k0 complete (k0+1 may still be in flight)
        __syncthreads();         // single barrier per k-iter
        int st = k0 % GEMM_STAGES;
#pragma unroll
        for (int ks = 0; ks < 2; ks++) {
            int kk = ks * 8;
            unsigned af[4][4], bf[4][2];
#pragma unroll
            for (int mi = 0; mi < 4; mi++) {
                int rb = wRow * 64 + mi * 16;
                af[mi][0] = __float_as_uint(As[st][rb + g][kk + t4]);
                af[mi][1] = __float_as_uint(As[st][rb + 8 + g][kk + t4]);
                af[mi][2] = __float_as_uint(As[st][rb + g][kk + 4 + t4]);
                af[mi][3] = __float_as_uint(As[st][rb + 8 + g][kk + 4 + t4]);
            }
#pragma unroll
            for (int ni = 0; ni < 4; ni++) {
                int cb = wCol * 32 + ni * 8 + g;
                bf[ni][0] = __float_as_uint(Bs[st][kk + t4][cb]);
                bf[ni][1] = __float_as_uint(Bs[st][kk + 4 + t4][cb]);
            }
#pragma unroll
            for (int mi = 0; mi < 4; mi++)
#pragma unroll
                for (int ni = 0; ni < 4; ni++) mma_tf32(acc[mi][ni], af[mi], bf[ni]);
        }
        // prefetch stage k0+2: writes (k0+2)%3 == (k0-1)%3, whose readers all
        // passed the barrier at the top of this iteration -> safe.
        if (k0 + 2 < nk) prefetch((k0 + 2) % GEMM_STAGES, k0 + 2);
        else cpa_commit();
    }

    if (doStats) {
        sstat[tid] = 0.f;
        __syncthreads();
    }
#pragma unroll
    for (int mi = 0; mi < 4; mi++) {
#pragma unroll
        for (int ni = 0; ni < 4; ni++) {
            int row = row0 + wRow * 64 + mi * 16 + g;
            int colL = wCol * 32 + ni * 8 + t4 * 2;
            int col = col0 + colL;
            float b0 = bias[col], b1 = bias[col + 1];
            float v0 = acc[mi][ni][0] + b0, v1 = acc[mi][ni][1] + b1;
            float v2 = acc[mi][ni][2] + b0, v3 = acc[mi][ni][3] + b1;
            bool ok0 = row < N, ok1 = row + 8 < N;
            if (ok0) {
                C[(size_t)row * M + col] = v0;
                C[(size_t)row * M + col + 1] = v1;
            }
            if (ok1) {
                C[(size_t)(row + 8) * M + col] = v2;
                C[(size_t)(row + 8) * M + col + 1] = v3;
            }
            if (doStats) {
                float s0 = (ok0 ? v0 : 0.f) + (ok1 ? v2 : 0.f);
                float s1 = (ok0 ? v1 : 0.f) + (ok1 ? v3 : 0.f);
                float q0 = (ok0 ? v0 * v0 : 0.f) + (ok1 ? v2 * v2 : 0.f);
                float q1 = (ok0 ? v1 * v1 : 0.f) + (ok1 ? v3 * v3 : 0.f);
                atomicAdd(&sstat[colL], s0);
                atomicAdd(&sstat[colL + 1], s1);
                atomicAdd(&sstat[128 + colL], q0);
                atomicAdd(&sstat[128 + colL + 1], q1);
            }
        }
    }
    if (doStats) {
        __syncthreads();
        if (tid < 128) {
            atomicAdd(&d_stat[col0 + tid], sstat[tid]);
            atomicAdd(&d_stat[256 + col0 + tid], sstat[128 + tid]);
        }
    }
}

__global__ void k_scale_shift(const float* __restrict__ g, const float* __restrict__ be,
                              int N, int F) {
    int f = blockIdx.x * blockDim.x + threadIdx.x;
    if (f < F) {
        float inv_n = 1.f / (float)N;
        float mean = d_stat[f] * inv_n;
        float var = d_stat[256 + f] * inv_n - mean * mean;
        float sc = g[f] * rsqrtf(var + EPS_BN);
        d_stat[512 + f] = sc;
        d_stat[768 + f] = be[f] - mean * sc;
    }
    if (f < 256) {
        d_stat[f] = 0.f;
        d_stat[256 + f] = 0.f;
    }
}

__global__ void k_zero_cnt(int G) {
    int i = blockIdx.x * blockDim.x + threadIdx.x;
    if (i < G) d_cnt[i] = 0u;
}
__global__ void k_cnt(int N) {
    int i = blockIdx.x * blockDim.x + threadIdx.x;
    if (i < N) atomicAdd(&d_cnt[d_batch32[i]], 1u);
}
__global__ void __launch_bounds__(256) k_pool2() {
    int gId = blockIdx.x;
    int f = threadIdx.x;
    int beg = d_goff[gId];
    int cnt = (int)d_cnt[gId];
    float sc = d_stat[512 + f], sh = d_stat[768 + f];
    float s = 0.f;
    for (int j = 0; j < cnt; j++) {
        float v = d_hB[(size_t)(beg + j) * 256 + f];
        s += fmaxf(fmaf(v, sc, sh), 0.f);
    }
    float inv = 1.f / (float)(cnt > 0 ? cnt : 1);
    d_pool[(size_t)gId * 256 + f] = f2tf_f(s * inv);
}

static inline int blk(int n, int t) { return (n + t - 1) / t; }

extern "C" void kernel_launch(void* const* d_in, const int* in_sizes, int n_in,
                              void* d_out, int out_size) {
    const float* x = (const float*)d_in[0];
    const void* ei = d_in[1];
    const void* batch = d_in[2];
    const int base = n_in - 14;
    const float* W1 = (const float*)d_in[base + 0];
    const float* b1 = (const float*)d_in[base + 1];
    const float* g1 = (const float*)d_in[base + 2];
    const float* be1 = (const float*)d_in[base + 3];
    const float* W2 = (const float*)d_in[base + 4];
    const float* b2 = (const float*)d_in[base + 5];
    const float* g2 = (const float*)d_in[base + 6];
    const float* be2 = (const float*)d_in[base + 7];
    const float* W3 = (const float*)d_in[base + 8];
    const float* b3 = (const float*)d_in[base + 9];
    const float* g3 = (const float*)d_in[base + 10];
    const float* be3 = (const float*)d_in[base + 11];
    const float* Wp = (const float*)d_in[base + 12];
    const float* bp = (const float*)d_in[base + 13];

    const int N = in_sizes[0] / 9;
    const int E = in_sizes[1] / 2;
    const int G = out_size / 256;
    const int T = 256;
    const int nb = blk(N, 256);
    const int nbg = blk(G, 256);

    cudaFuncSetAttribute(k_gemm_tf32, cudaFuncAttributeMaxDynamicSharedMemorySize,
                         GEMM_SMEM);

    // --- weight pre-rounding (dst selected device-side) ---
    k_roundW<<<blk(128 * 256, T), T>>>(W2, 0, 128 * 256);
    k_roundW<<<blk(256 * 256, T), T>>>(W3, 1, 256 * 256);
    k_roundW<<<blk(256 * 256, T), T>>>(Wp, 2, 256 * 256);

    // --- index conversion + degrees / norm ---
    k_sniff<<<1, 1>>>(ei);
    k_conv_ei<<<blk(2 * E, T), T>>>(ei, 2 * E);
    k_conv_batch<<<blk(N, T), T>>>(batch, N);
    k_count_deg<<<blk(E, T), T>>>(E);
    k_dis<<<blk(N, T), T>>>(N);

    // --- CSR by destination ---
    k_scan1<<<nb, 256>>>(N);
    k_scan2<<<1, 32>>>(nb);
    k_scan3<<<nb, 256>>>(N);
    k_fill<<<blk(E, T), T>>>(E);

    // --- layer 1 ---
    k_gather9<<<blk(N, T), T>>>(x, N);
    k_gemm1<<<blk(N, 64), 256>>>(W1, b1, N);
    k_scale_shift<<<1, 256>>>(g1, be1, N, 128);

    // --- layer 2 ---
    k_gather<<<blk(N, 8), 256>>>(N, 128);
    {
        dim3 grid(blk(N, 128), 2);
        k_gemm_tf32<<<grid, 256, GEMM_SMEM>>>(0, 0, b2, nullptr, 0, 1, N, 128, 256);
    }
    k_scale_shift<<<1, 256>>>(g2, be2, N, 256);

    // --- layer 3 ---
    k_gather<<<blk(N, 8), 256>>>(N, 256);
    {
        dim3 grid(blk(N, 128), 2);
        k_gemm_tf32<<<grid, 256, GEMM_SMEM>>>(0, 1, b3, nullptr, 0, 1, N, 256, 256);
    }
    k_scale_shift<<<1, 256>>>(g3, be3, N, 256);

    // --- segmented mean pool ---
    k_zero_cnt<<<nbg, 256>>>(G);
    k_cnt<<<blk(N, T), T>>>(N);
    k_gscan1<<<nbg, 256>>>(G);
    k_gscan2<<<1, 32>>>(nbg);
    k_gscan3<<<nbg, 256>>>(G);
    k_pool2<<<G, 256>>>();

    // --- final linear ---
    {
        dim3 grid(blk(G, 128), 2);
        k_gemm_tf32<<<grid, 256, GEMM_SMEM>>>(1, 2, bp, (float*)d_out, 1, 0, G, 256, 256);
    }
}

// round 14
// speedup vs baseline: 1.0842x; 1.0180x over previous
#include <cuda_runtime.h>

// ---------------- static scratch (no allocation allowed) ----------------
#define NMAX 200000
#define EMAX 400000
#define FMAX 256
#define GMAX 8192
#define EPS_BN 1e-5f

__device__ float d_hA[(size_t)NMAX * FMAX];
__device__ float d_hB[(size_t)NMAX * FMAX];
__device__ float d_dis[NMAX];
__device__ unsigned int d_deg[NMAX];
__device__ float d_stat[4 * FMAX];
__device__ float d_pool[(size_t)GMAX * FMAX];
__device__ float d_Wt2[128 * 256];
__device__ float d_Wt3[256 * 256];
__device__ float d_Wtp[256 * 256];
__device__ unsigned int d_cnt[GMAX];
__device__ int d_goff[GMAX];
__device__ int d_ei32[2 * EMAX];
__device__ int d_batch32[NMAX];
__device__ int d_is64;
__device__ int d_off[NMAX];
__device__ unsigned int d_cur[NMAX];
__device__ int d_srcs[EMAX];
__device__ int d_bsum[1024];
__device__ int d_bsum2[64];

__device__ __forceinline__ float f2tf_f(float f) {
    unsigned r;
    asm("cvt.rna.tf32.f32 %0, %1;" : "=r"(r) : "f"(f));
    return __uint_as_float(r);
}
__device__ __forceinline__ unsigned smem_u32(const void* p) {
    return (unsigned)__cvta_generic_to_shared(p);
}
__device__ __forceinline__ void cpa16(unsigned dst, const void* src, bool pred) {
    int sz = pred ? 16 : 0;
    asm volatile("cp.async.ca.shared.global [%0], [%1], 16, %2;\n"
                 :: "r"(dst), "l"(src), "r"(sz));
}
__device__ __forceinline__ void cpa_commit() { asm volatile("cp.async.commit_group;\n"); }
template <int NWait>
__device__ __forceinline__ void cpa_wait() { asm volatile("cp.async.wait_group %0;\n" :: "n"(NWait)); }

__device__ __forceinline__ void mma_tf32(float* c, const unsigned* a, const unsigned* b) {
    asm volatile(
        "mma.sync.aligned.m16n8k8.row.col.f32.tf32.tf32.f32 "
        "{%0,%1,%2,%3}, {%4,%5,%6,%7}, {%8,%9}, {%0,%1,%2,%3};"
        : "+f"(c[0]), "+f"(c[1]), "+f"(c[2]), "+f"(c[3])
        : "r"(a[0]), "r"(a[1]), "r"(a[2]), "r"(a[3]), "r"(b[0]), "r"(b[1]));
}

__global__ void k_sniff(const void* ei) {
    const int* p = (const int*)ei;
    int ok64 = 1;
    for (int j = 0; j < 64; j++)
        if (p[2 * j + 1] != 0) ok64 = 0;
    d_is64 = ok64;
}
// also zeroes d_cnt (counted later in k_conv_batch)
__global__ void k_conv_ei(const void* ei, int E2, int G) {
    int i = blockIdx.x * blockDim.x + threadIdx.x;
    if (i < E2)
        d_ei32[i] = d_is64 ? (int)((const long long*)ei)[i] : ((const int*)ei)[i];
    if (i < G) d_cnt[i] = 0u;
}
// converts batch indices AND counts nodes per graph
__global__ void k_conv_batch(const void* b, int N) {
    int i = blockIdx.x * blockDim.x + threadIdx.x;
    if (i < N) {
        int g = d_is64 ? (int)((const long long*)b)[i] : ((const int*)b)[i];
        d_batch32[i] = g;
        atomicAdd(&d_cnt[g], 1u);
        d_deg[i] = 1u;
        d_cur[i] = 0u;
    }
    if (i < 512) d_stat[i] = 0.f;
}

// dst resolved IN DEVICE CODE (host must never touch __device__ symbols)
__global__ void k_roundW(const float* __restrict__ W, int sel, int n) {
    int i = blockIdx.x * blockDim.x + threadIdx.x;
    if (i < n) {
        float* dst = (sel == 0) ? d_Wt2 : (sel == 1 ? d_Wt3 : d_Wtp);
        dst[i] = f2tf_f(W[i]);
    }
}

__global__ void k_count_deg(int E) {
    int e = blockIdx.x * blockDim.x + threadIdx.x;
    if (e < E) atomicAdd(&d_deg[d_ei32[E + e]], 1u);
}
__global__ void k_dis(int N) {
    int i = blockIdx.x * blockDim.x + threadIdx.x;
    if (i < N) d_dis[i] = rsqrtf((float)d_deg[i]);
}

__global__ void k_scan1(int N) {
    __shared__ int sh[256];
    int i = blockIdx.x * 256 + threadIdx.x;
    int v = (i < N) ? (int)d_deg[i] - 1 : 0;
    sh[threadIdx.x] = v;
    __syncthreads();
    for (int o = 128; o > 0; o >>= 1) {
        if (threadIdx.x < o) sh[threadIdx.x] += sh[threadIdx.x + o];
        __syncthreads();
    }
    if (threadIdx.x == 0) d_bsum[blockIdx.x] = sh[0];
}
__global__ void k_scan2(int nb) {
    if (threadIdx.x == 0 && blockIdx.x == 0) {
        int run = 0;
        for (int b = 0; b < nb; b++) { int t = d_bsum[b]; d_bsum[b] = run; run += t; }
    }
}
__global__ void k_scan3(int N) {
    __shared__ int sh[256];
    int i = blockIdx.x * 256 + threadIdx.x;
    int v = (i < N) ? (int)d_deg[i] - 1 : 0;
    sh[threadIdx.x] = v;
    __syncthreads();
    for (int o = 1; o < 256; o <<= 1) {
        int t = (threadIdx.x >= o) ? sh[threadIdx.x - o] : 0;
        __syncthreads();
        sh[threadIdx.x] += t;
        __syncthreads();
    }
    if (i < N) d_off[i] = d_bsum[blockIdx.x] + sh[threadIdx.x] - v;
}
__global__ void k_fill(int E) {
    int e = blockIdx.x * blockDim.x + threadIdx.x;
    if (e < E) {
        int s = d_ei32[e], d = d_ei32[E + e];
        int pos = d_off[d] + (int)atomicAdd(&d_cur[d], 1u);
        d_srcs[pos] = s;
    }
}

__global__ void k_gscan1(int G) {
    __shared__ int sh[256];
    int i = blockIdx.x * 256 + threadIdx.x;
    int v = (i < G) ? (int)d_cnt[i] : 0;
    sh[threadIdx.x] = v;
    __syncthreads();
    for (int o = 128; o > 0; o >>= 1) {
        if (threadIdx.x < o) sh[threadIdx.x] += sh[threadIdx.x + o];
        __syncthreads();
    }
    if (threadIdx.x == 0) d_bsum2[blockIdx.x] = sh[0];
}
__global__ void k_gscan2(int nb) {
    if (threadIdx.x == 0 && blockIdx.x == 0) {
        int run = 0;
        for (int b = 0; b < nb; b++) { int t = d_bsum2[b]; d_bsum2[b] = run; run += t; }
    }
}
__global__ void k_gscan3(int G) {
    __shared__ int sh[256];
    int i = blockIdx.x * 256 + threadIdx.x;
    int v = (i < G) ? (int)d_cnt[i] : 0;
    sh[threadIdx.x] = v;
    __syncthreads();
    for (int o = 1; o < 256; o <<= 1) {
        int t = (threadIdx.x >= o) ? sh[threadIdx.x - o] : 0;
        __syncthreads();
        sh[threadIdx.x] += t;
        __syncthreads();
    }
    if (i < G) d_goff[i] = d_bsum2[blockIdx.x] + sh[threadIdx.x] - v;
}

__global__ void k_gather9(const float* __restrict__ x, int N) {
    int i = blockIdx.x * blockDim.x + threadIdx.x;
    if (i >= N) return;
    float di = d_dis[i];
    float acc[9];
    const float* xi = x + (size_t)i * 9;
#pragma unroll
    for (int f = 0; f < 9; f++) acc[f] = di * di * xi[f];
    int beg = d_off[i], cnt = (int)d_deg[i] - 1;
    for (int j = 0; j < cnt; j++) {
        int s = d_srcs[beg + j];
        float w = d_dis[s] * di;
        const float* xs = x + (size_t)s * 9;
#pragma unroll
        for (int f = 0; f < 9; f++) acc[f] += w * xs[f];
    }
    float* o = d_hA + (size_t)i * 9;
#pragma unroll
    for (int f = 0; f < 9; f++) o[f] = acc[f];
}
// warp per node, BN+ReLU fused, tf32-rounded output; neighbor loop unrolled x2.
__global__ void k_gather(int N, int F) {
    int w = (blockIdx.x * blockDim.x + threadIdx.x) >> 5;
    int lane = threadIdx.x & 31;
    if (w >= N) return;
    int C4 = F >> 7;
    float di = d_dis[w];
    float4 sc[2], sh[2], acc[2];
#pragma unroll
    for (int c = 0; c < 2; c++) {
        if (c < C4) {
            int col = c * 128 + lane * 4;
            sc[c] = *(const float4*)&d_stat[512 + col];
            sh[c] = *(const float4*)&d_stat[768 + col];
        }
    }
    {
        float ww = di * di;
        const float4* row = (const float4*)(d_hB + (size_t)w * F);
#pragma unroll
        for (int c = 0; c < 2; c++) {
            if (c < C4) {
                float4 v = row[c * 32 + lane];
                acc[c].x = ww * fmaxf(fmaf(v.x, sc[c].x, sh[c].x), 0.f);
                acc[c].y = ww * fmaxf(fmaf(v.y, sc[c].y, sh[c].y), 0.f);
                acc[c].z = ww * fmaxf(fmaf(v.z, sc[c].z, sh[c].z), 0.f);
                acc[c].w = ww * fmaxf(fmaf(v.w, sc[c].w, sh[c].w), 0.f);
            }
        }
    }
    int beg = d_off[w], cnt = (int)d_deg[w] - 1;
    int j = 0;
    for (; j + 1 < cnt; j += 2) {
        int s0 = d_srcs[beg + j];
        int s1 = d_srcs[beg + j + 1];
        float w0 = d_dis[s0] * di;
        float w1 = d_dis[s1] * di;
        const float4* r0 = (const float4*)(d_hB + (size_t)s0 * F);
        const float4* r1 = (const float4*)(d_hB + (size_t)s1 * F);
#pragma unroll
        for (int c = 0; c < 2; c++) {
            if (c < C4) {
                float4 v0 = r0[c * 32 + lane];
                float4 v1 = r1[c * 32 + lane];
                acc[c].x = fmaf(w0, fmaxf(fmaf(v0.x, sc[c].x, sh[c].x), 0.f), acc[c].x);
                acc[c].y = fmaf(w0, fmaxf(fmaf(v0.y, sc[c].y, sh[c].y), 0.f), acc[c].y);
                acc[c].z = fmaf(w0, fmaxf(fmaf(v0.z, sc[c].z, sh[c].z), 0.f), acc[c].z);
                acc[c].w = fmaf(w0, fmaxf(fmaf(v0.w, sc[c].w, sh[c].w), 0.f), acc[c].w);
                acc[c].x = fmaf(w1, fmaxf(fmaf(v1.x, sc[c].x, sh[c].x), 0.f), acc[c].x);
                acc[c].y = fmaf(w1, fmaxf(fmaf(v1.y, sc[c].y, sh[c].y), 0.f), acc[c].y);
                acc[c].z = fmaf(w1, fmaxf(fmaf(v1.z, sc[c].z, sh[c].z), 0.f), acc[c].z);
                acc[c].w = fmaf(w1, fmaxf(fmaf(v1.w, sc[c].w, sh[c].w), 0.f), acc[c].w);
            }
        }
    }
    if (j < cnt) {
        int s = d_srcs[beg + j];
        float we = d_dis[s] * di;
        const float4* row = (const float4*)(d_hB + (size_t)s * F);
#pragma unroll
        for (int c = 0; c < 2; c++) {
            if (c < C4) {
                float4 v = row[c * 32 + lane];
                acc[c].x = fmaf(we, fmaxf(fmaf(v.x, sc[c].x, sh[c].x), 0.f), acc[c].x);
                acc[c].y = fmaf(we, fmaxf(fmaf(v.y, sc[c].y, sh[c].y), 0.f), acc[c].y);
                acc[c].z = fmaf(we, fmaxf(fmaf(v.z, sc[c].z, sh[c].z), 0.f), acc[c].z);
                acc[c].w = fmaf(we, fmaxf(fmaf(v.w, sc[c].w, sh[c].w), 0.f), acc[c].w);
            }
        }
    }
    float4* o = (float4*)(d_hA + (size_t)w * F);
#pragma unroll
    for (int c = 0; c < 2; c++) {
        if (c < C4) {
            float4 r;
            r.x = f2tf_f(acc[c].x); r.y = f2tf_f(acc[c].y);
            r.z = f2tf_f(acc[c].z); r.w = f2tf_f(acc[c].w);
            o[c * 32 + lane] = r;
        }
    }
}

__global__ void __launch_bounds__(256) k_gemm1(const float* __restrict__ W,
                                               const float* __restrict__ b, int N) {
    __shared__ float sW[9 * 128];
    __shared__ float sb[128];
    __shared__ float sA[64 * 9];
    __shared__ float sstat[256];
    int tid = threadIdx.x;
    for (int i = tid; i < 9 * 128; i += 256) sW[i] = W[i];
    if (tid < 128) sb[tid] = b[tid];
    sstat[tid] = 0.f;
    int row0 = blockIdx.x * 64;
    for (int i = tid; i < 576; i += 256) {
        int r = i / 9, c = i - r * 9;
        int row = row0 + r;
        sA[i] = (row < N) ? d_hA[(size_t)row * 9 + c] : 0.f;
    }
    __syncthreads();
    int col = tid & 127, half = tid >> 7;
    float s = 0.f, ss = 0.f;
    for (int r = half * 32; r < half * 32 + 32; r++) {
        int row = row0 + r;
        float acc = sb[col];
#pragma unroll
        for (int k = 0; k < 9; k++) acc = fmaf(sA[r * 9 + k], sW[k * 128 + col], acc);
        if (row < N) {
            d_hB[(size_t)row * 128 + col] = acc;
            s += acc;
            ss += acc * acc;
        }
    }
    atomicAdd(&sstat[col], s);
    atomicAdd(&sstat[128 + col], ss);
    __syncthreads();
    if (tid < 128) {
        atomicAdd(&d_stat[tid], sstat[tid]);
        atomicAdd(&d_stat[256 + tid], sstat[128 + tid]);
    }
}

// ---------------- 3-stage pipelined TF32 GEMM, BK=16, single sync/iter ------
// grid = (M/128, ceil(N/128)): col blocks on x (adjacent ids share A tile in L2)
#define GEMM_STAGES 3
#define ASTR 20
#define BSTR 136
#define GEMM_SMEM (GEMM_STAGES * (128 * ASTR + 16 * BSTR) * 4)

__global__ void __launch_bounds__(256) k_gemm_tf32(int selA, int selB,
                                                   const float* __restrict__ bias,
                                                   float* Cext, int useExt, int doStats,
                                                   int N, int K, int M) {
    const float* A = selA ? d_pool : d_hA;
    const float* Wt = (selB == 0) ? d_Wt2 : (selB == 1 ? d_Wt3 : d_Wtp);
    float* C = useExt ? Cext : d_hB;
    extern __shared__ float smem[];
    float (*As)[128][ASTR] = (float (*)[128][ASTR])smem;
    float (*Bs)[16][BSTR] = (float (*)[16][BSTR])(smem + GEMM_STAGES * 128 * ASTR);
    __shared__ float sstat[256];

    int tid = threadIdx.x;
    int lane = tid & 31;
    int warp = tid >> 5;
    int wRow = warp & 1;
    int wCol = warp >> 1;
    int row0 = blockIdx.y * 128;   // rows on y
    int col0 = blockIdx.x * 128;   // cols on x (fastest-varying id)
    int g = lane >> 2;
    int t4 = lane & 3;
    int nk = K >> 4;

    float acc[4][4][4];
#pragma unroll
    for (int mi = 0; mi < 4; mi++)
#pragma unroll
        for (int ni = 0; ni < 4; ni++)
#pragma unroll
            for (int r = 0; r < 4; r++) acc[mi][ni][r] = 0.f;

    int rA0 = tid >> 2, cA0 = (tid & 3) << 2;
    int rA1 = (tid + 256) >> 2, cA1 = cA0;
    int rB0 = tid >> 5, cB0 = (tid & 31) << 2;
    int rB1 = rB0 + 8, cB1 = cB0;

    auto prefetch = [&](int st, int k0) {
        const float* a0 = &A[(size_t)(row0 + rA0) * K + k0 * 16 + cA0];
        const float* a1 = &A[(size_t)(row0 + rA1) * K + k0 * 16 + cA1];
        cpa16(smem_u32(&As[st][rA0][cA0]), a0, row0 + rA0 < N);
        cpa16(smem_u32(&As[st][rA1][cA1]), a1, row0 + rA1 < N);
        const float* b0 = &Wt[(size_t)(k0 * 16 + rB0) * M + col0 + cB0];
        const float* b1 = &Wt[(size_t)(k0 * 16 + rB1) * M + col0 + cB1];
        cpa16(smem_u32(&Bs[st][rB0][cB0]), b0, true);
        cpa16(smem_u32(&Bs[st][rB1][cB1]), b1, true);
        cpa_commit();
    };

    prefetch(0, 0);
    if (nk > 1) prefetch(1, 1); else cpa_commit();

    for (int k0 = 0; k0 < nk; k0++) {
        cpa_wait<1>();
        __syncthreads();
        int st = k0 % GEMM_STAGES;
#pragma unroll
        for (int ks = 0; ks < 2; ks++) {
            int kk = ks * 8;
            unsigned af[4][4], bf[4][2];
#pragma unroll
            for (int mi = 0; mi < 4; mi++) {
                int rb = wRow * 64 + mi * 16;
                af[mi][0] = __float_as_uint(As[st][rb + g][kk + t4]);
                af[mi][1] = __float_as_uint(As[st][rb + 8 + g][kk + t4]);
                af[mi][2] = __float_as_uint(As[st][rb + g][kk + 4 + t4]);
                af[mi][3] = __float_as_uint(As[st][rb + 8 + g][kk + 4 + t4]);
            }
#pragma unroll
            for (int ni = 0; ni < 4; ni++) {
                int cb = wCol * 32 + ni * 8 + g;
                bf[ni][0] = __float_as_uint(Bs[st][kk + t4][cb]);
                bf[ni][1] = __float_as_uint(Bs[st][kk + 4 + t4][cb]);
            }
#pragma unroll
            for (int mi = 0; mi < 4; mi++)
#pragma unroll
                for (int ni = 0; ni < 4; ni++) mma_tf32(acc[mi][ni], af[mi], bf[ni]);
        }
        if (k0 + 2 < nk) prefetch((k0 + 2) % GEMM_STAGES, k0 + 2);
        else cpa_commit();
    }

    if (doStats) {
        sstat[tid] = 0.f;
        __syncthreads();
    }
#pragma unroll
    for (int mi = 0; mi < 4; mi++) {
#pragma unroll
        for (int ni = 0; ni < 4; ni++) {
            int row = row0 + wRow * 64 + mi * 16 + g;
            int colL = wCol * 32 + ni * 8 + t4 * 2;
            int col = col0 + colL;
            float b0 = bias[col], b1 = bias[col + 1];
            float v0 = acc[mi][ni][0] + b0, v1 = acc[mi][ni][1] + b1;
            float v2 = acc[mi][ni][2] + b0, v3 = acc[mi][ni][3] + b1;
            bool ok0 = row < N, ok1 = row + 8 < N;
            if (ok0) {
                C[(size_t)row * M + col] = v0;
                C[(size_t)row * M + col + 1] = v1;
            }
            if (ok1) {
                C[(size_t)(row + 8) * M + col] = v2;
                C[(size_t)(row + 8) * M + col + 1] = v3;
            }
            if (doStats) {
                float s0 = (ok0 ? v0 : 0.f) + (ok1 ? v2 : 0.f);
                float s1 = (ok0 ? v1 : 0.f) + (ok1 ? v3 : 0.f);
                float q0 = (ok0 ? v0 * v0 : 0.f) + (ok1 ? v2 * v2 : 0.f);
                float q1 = (ok0 ? v1 * v1 : 0.f) + (ok1 ? v3 * v3 : 0.f);
                atomicAdd(&sstat[colL], s0);
                atomicAdd(&sstat[colL + 1], s1);
                atomicAdd(&sstat[128 + colL], q0);
                atomicAdd(&sstat[128 + colL + 1], q1);
            }
        }
    }
    if (doStats) {
        __syncthreads();
        if (tid < 128) {
            atomicAdd(&d_stat[col0 + tid], sstat[tid]);
            atomicAdd(&d_stat[256 + col0 + tid], sstat[128 + tid]);
        }
    }
}

__global__ void k_scale_shift(const float* __restrict__ g, const float* __restrict__ be,
                              int N, int F) {
    int f = blockIdx.x * blockDim.x + threadIdx.x;
    if (f < F) {
        float inv_n = 1.f / (float)N;
        float mean = d_stat[f] * inv_n;
        float var = d_stat[256 + f] * inv_n - mean * mean;
        float sc = g[f] * rsqrtf(var + EPS_BN);
        d_stat[512 + f] = sc;
        d_stat[768 + f] = be[f] - mean * sc;
    }
    if (f < 256) {
        d_stat[f] = 0.f;
        d_stat[256 + f] = 0.f;
    }
}

// segmented mean pool with BN3+ReLU fused; segment loop unrolled x4
__global__ void __launch_bounds__(256) k_pool2() {
    int gId = blockIdx.x;
    int f = threadIdx.x;
    int beg = d_goff[gId];
    int cnt = (int)d_cnt[gId];
    float sc = d_stat[512 + f], sh = d_stat[768 + f];
    float s = 0.f;
    int j = 0;
    for (; j + 3 < cnt; j += 4) {
        float v0 = d_hB[(size_t)(beg + j + 0) * 256 + f];
        float v1 = d_hB[(size_t)(beg + j + 1) * 256 + f];
        float v2 = d_hB[(size_t)(beg + j + 2) * 256 + f];
        float v3 = d_hB[(size_t)(beg + j + 3) * 256 + f];
        s += fmaxf(fmaf(v0, sc, sh), 0.f);
        s += fmaxf(fmaf(v1, sc, sh), 0.f);
        s += fmaxf(fmaf(v2, sc, sh), 0.f);
        s += fmaxf(fmaf(v3, sc, sh), 0.f);
    }
    for (; j < cnt; j++) {
        float v = d_hB[(size_t)(beg + j) * 256 + f];
        s += fmaxf(fmaf(v, sc, sh), 0.f);
    }
    float inv = 1.f / (float)(cnt > 0 ? cnt : 1);
    d_pool[(size_t)gId * 256 + f] = f2tf_f(s * inv);
}

static inline int blk(int n, int t) { return (n + t - 1) / t; }

extern "C" void kernel_launch(void* const* d_in, const int* in_sizes, int n_in,
                              void* d_out, int out_size) {
    const float* x = (const float*)d_in[0];
    const void* ei = d_in[1];
    const void* batch = d_in[2];
    const int base = n_in - 14;
    const float* W1 = (const float*)d_in[base + 0];
    const float* b1 = (const float*)d_in[base + 1];
    const float* g1 = (const float*)d_in[base + 2];
    const float* be1 = (const float*)d_in[base + 3];
    const float* W2 = (const float*)d_in[base + 4];
    const float* b2 = (const float*)d_in[base + 5];
    const float* g2 = (const float*)d_in[base + 6];
    const float* be2 = (const float*)d_in[base + 7];
    const float* W3 = (const float*)d_in[base + 8];
    const float* b3 = (const float*)d_in[base + 9];
    const float* g3 = (const float*)d_in[base + 10];
    const float* be3 = (const float*)d_in[base + 11];
    const float* Wp = (const float*)d_in[base + 12];
    const float* bp = (const float*)d_in[base + 13];

    const int N = in_sizes[0] / 9;
    const int E = in_sizes[1] / 2;
    const int G = out_size / 256;
    const int T = 256;
    const int nb = blk(N, 256);
    const int nbg = blk(G, 256);

    cudaFuncSetAttribute(k_gemm_tf32, cudaFuncAttributeMaxDynamicSharedMemorySize,
                         GEMM_SMEM);

    // --- weight pre-rounding (dst selected device-side) ---
    k_roundW<<<blk(128 * 256, T), T>>>(W2, 0, 128 * 256);
    k_roundW<<<blk(256 * 256, T), T>>>(W3, 1, 256 * 256);
    k_roundW<<<blk(256 * 256, T), T>>>(Wp, 2, 256 * 256);

    // --- index conversion (+cnt zero/count) + degrees / norm ---
    k_sniff<<<1, 1>>>(ei);
    k_conv_ei<<<blk(2 * E, T), T>>>(ei, 2 * E, G);
    k_conv_batch<<<blk(N, T), T>>>(batch, N);
    // graph offsets ready early (depends only on d_cnt)
    k_gscan1<<<nbg, 256>>>(G);
    k_gscan2<<<1, 32>>>(nbg);
    k_gscan3<<<nbg, 256>>>(G);
    k_count_deg<<<blk(E, T), T>>>(E);
    k_dis<<<blk(N, T), T>>>(N);

    // --- CSR by destination ---
    k_scan1<<<nb, 256>>>(N);
    k_scan2<<<1, 32>>>(nb);
    k_scan3<<<nb, 256>>>(N);
    k_fill<<<blk(E, T), T>>>(E);

    // --- layer 1 ---
    k_gather9<<<blk(N, T), T>>>(x, N);
    k_gemm1<<<blk(N, 64), 256>>>(W1, b1, N);
    k_scale_shift<<<1, 256>>>(g1, be1, N, 128);

    // --- layer 2 ---
    k_gather<<<blk(N, 8), 256>>>(N, 128);
    {
        dim3 grid(2, blk(N, 128));
        k_gemm_tf32<<<grid, 256, GEMM_SMEM>>>(0, 0, b2, nullptr, 0, 1, N, 128, 256);
    }
    k_scale_shift<<<1, 256>>>(g2, be2, N, 256);

    // --- layer 3 ---
    k_gather<<<blk(N, 8), 256>>>(N, 256);
    {
        dim3 grid(2, blk(N, 128));
        k_gemm_tf32<<<grid, 256, GEMM_SMEM>>>(0, 1, b3, nullptr, 0, 1, N, 256, 256);
    }
    k_scale_shift<<<1, 256>>>(g3, be3, N, 256);

    // --- segmented mean pool ---
    k_pool2<<<G, 256>>>();

    // --- final linear ---
    {
        dim3 grid(2, blk(G, 128));
        k_gemm_tf32<<<grid, 256, GEMM_SMEM>>>(1, 2, bp, (float*)d_out, 1, 0, G, 256, 256);
    }
}